// round 10
// baseline (speedup 1.0000x reference)
#include <cuda_runtime.h>
#include <cuda_fp16.h>
#include <cstdint>
#include <math.h>

// ---------------- problem constants ----------------
#define NB    128
#define TCAP  31
#define TSTEP 30
#define CIN   1280
#define WD    512
#define HD    1024
#define VOC   10000
#define VOCP  10240
#define NROW  (TSTEP*NB)
#define KSPLIT 4

#define SROW 40                      // smem row stride in halves (80B)
#define NSTAGE 3
#define DYN_SMEM_128 (NSTAGE * (128 + 128) * SROW * 2)   // 61440
#define DYN_SMEM_64  (NSTAGE * (128 + 64) * SROW * 2)    // 46080

// ---------------- device scratch ----------------
__device__ float g_A[NB * 16 * HD];
__device__ float g_hx[NB * HD];
__device__ float g_c[NB * HD];
__device__ float g_xa[NROW * 4 * HD];
__device__ float g_apart[KSPLIT * NB * 4 * HD];
__device__ unsigned long long g_rowms[NROW];
__device__ float g_tgtlog[NROW];
__device__ int   g_tgt[NROW];
__device__ float g_loss;

__device__ __align__(256) __half g_WpT[HD * CIN];
__device__ __align__(256) __half g_WxT[4 * HD * WD];
__device__ __align__(256) __half g_WhaT[4 * HD * 2 * HD];
__device__ __align__(256) __half g_WvT[VOCP * HD];
__device__ __align__(256) __half g_Ai[NB * 16 * CIN];
__device__ __align__(256) __half g_X[NROW * WD];
__device__ __align__(256) __half g_hxh[NB * 2 * HD];
__device__ __align__(256) __half g_hsh[NROW * HD];

// ---------------- tiny utils ----------------
__global__ void k_zero() { g_loss = 0.f; }
__global__ void k_final(float* __restrict__ out) { out[0] = g_loss * (1.0f / (float)NB); }

__device__ __forceinline__ uint32_t smem_u32(const void* p) {
    uint32_t a;
    asm("{ .reg .u64 t; cvta.to.shared.u64 t, %1; cvt.u32.u64 %0, t; }" : "=r"(a) : "l"(p));
    return a;
}
__device__ __forceinline__ float fast_sigmoid(float x) {
    return 1.0f / (1.0f + __expf(-x));
}
__device__ __forceinline__ float fast_tanh(float x) {
    float xc = fminf(fmaxf(x, -15.f), 15.f);
    float e = __expf(2.0f * xc);
    return (e - 1.0f) / (e + 1.0f);
}

__global__ void k_prep(const int* __restrict__ captions) {
    int m = blockIdx.x * blockDim.x + threadIdx.x;
    if (m >= NROW) return;
    int t = m >> 7, n = m & 127;
    g_tgt[m] = captions[n * TCAP + t + 1];
    g_rowms[m] = ((unsigned long long)__float_as_uint(-1e30f) << 32) | __float_as_uint(0.f);
}

// ---------------- weight transpose fp32[K][N] -> fp16[N][dld] ----------------
__global__ void k_convT(const float* __restrict__ src, int K, int N,
                        __half* __restrict__ dst, int dld, int koff) {
    __shared__ float t[32][33];
    const int nb = blockIdx.x * 32, kb = blockIdx.y * 32;
    const int tx = threadIdx.x, ty = threadIdx.y;
#pragma unroll
    for (int i = 0; i < 4; i++) {
        int k = kb + ty + i * 8, n = nb + tx;
        t[ty + i * 8][tx] = (n < N && k < K) ? src[(size_t)k * N + n] : 0.f;
    }
    __syncthreads();
#pragma unroll
    for (int i = 0; i < 4; i++) {
        int n = nb + ty + i * 8, k = kb + tx;
        dst[(size_t)n * dld + koff + k] = __float2half(t[tx][ty + i * 8]);
    }
}

__global__ void k_conv_images(const float* __restrict__ images) {
    int idx = blockIdx.x * blockDim.x + threadIdx.x;
    if (idx >= NB * 16 * CIN) return;
    int m = idx / CIN, c = idx - m * CIN;
    g_Ai[idx] = __float2half(images[((size_t)(m >> 4) * CIN + c) * 16 + (m & 15)]);
}

__global__ void k_conv_embed(const int* __restrict__ captions,
                             const float* __restrict__ We) {
    int idx = blockIdx.x * blockDim.x + threadIdx.x;
    if (idx >= NROW * WD) return;
    int m = idx / WD, k = idx - m * WD;
    int t = m >> 7, n = m & 127;
    g_X[idx] = __float2half(We[(size_t)captions[n * TCAP + t] * WD + k]);
}

// ---------------- templated fp16 mma.sync mainloop (3-stage cp.async) ----------------
// A tile 128 rows, B tile BN rows (BN in {64,128}); d[2][BN/16][4]
template <int BN>
__device__ __forceinline__ void gemm_mainloop(
    const __half* __restrict__ Aop, const __half* __restrict__ Bop,
    int Kld, int Klen, int koff, int m0, int n0,
    __half* dynsm, float d[2][BN / 16][4]) {
    constexpr int BJ = BN / 32;                       // per-warp 16-col groups
    constexpr int STB = (128 + BN) * SROW * 2;        // stage bytes
    const int tid = threadIdx.x;
    const int wid = tid >> 5, lane = tid & 31;
    const int wm = (wid & 3) * 32;
    const int wn = (wid >> 2) * (BN / 2);
    const int KT = Klen >> 5;
    const uint32_t sbase = smem_u32(dynsm);
    const int lrow = lane & 15, lcol = lane >> 4;

#pragma unroll
    for (int i = 0; i < 2; i++)
#pragma unroll
        for (int j = 0; j < BN / 16; j++)
#pragma unroll
            for (int q = 0; q < 4; q++) d[i][j][q] = 0.f;

    auto issue = [&](int kt) {
        const int stage = kt % NSTAGE;
        const uint32_t ab = sbase + (uint32_t)stage * STB;
        const uint32_t bb = ab + 128 * SROW * 2;
        const int k0 = koff + (kt << 5);
#pragma unroll
        for (int i = 0; i < 2; i++) {
            int c = tid + i * 256;
            int r = c >> 2, seg = c & 3;
            const void* gp = Aop + (size_t)(m0 + r) * Kld + k0 + seg * 8;
            uint32_t sp = ab + (uint32_t)(r * SROW * 2 + seg * 16);
            asm volatile("cp.async.cg.shared.global [%0], [%1], 16;" :: "r"(sp), "l"(gp));
        }
#pragma unroll
        for (int i = 0; i < BN / 64; i++) {
            int c = tid + i * 256;
            int r = c >> 2, seg = c & 3;
            const void* gp = Bop + (size_t)(n0 + r) * Kld + k0 + seg * 8;
            uint32_t sp = bb + (uint32_t)(r * SROW * 2 + seg * 16);
            asm volatile("cp.async.cg.shared.global [%0], [%1], 16;" :: "r"(sp), "l"(gp));
        }
        asm volatile("cp.async.commit_group;");
    };

    issue(0);
    if (KT > 1) issue(1);
    for (int kt = 0; kt < KT; kt++) {
        if (kt + 2 < KT) {
            issue(kt + 2);
            asm volatile("cp.async.wait_group 2;");
        } else if (kt + 1 < KT) {
            asm volatile("cp.async.wait_group 1;");
        } else {
            asm volatile("cp.async.wait_group 0;");
        }
        __syncthreads();
        const int stage = kt % NSTAGE;
        const uint32_t ab = sbase + (uint32_t)stage * STB;
        const uint32_t bb = ab + 128 * SROW * 2;
#pragma unroll
        for (int ks = 0; ks < 2; ks++) {
            uint32_t af[2][4];
#pragma unroll
            for (int mi = 0; mi < 2; mi++) {
                uint32_t addr = ab + (uint32_t)((wm + mi * 16 + lrow) * SROW * 2
                                                + lcol * 16 + ks * 32);
                asm volatile("ldmatrix.sync.aligned.m8n8.x4.shared.b16 {%0,%1,%2,%3}, [%4];"
                             : "=r"(af[mi][0]), "=r"(af[mi][1]), "=r"(af[mi][2]), "=r"(af[mi][3])
                             : "r"(addr));
            }
#pragma unroll
            for (int bj = 0; bj < BJ; bj++) {
                uint32_t bf[4];
                uint32_t addr = bb + (uint32_t)((wn + bj * 16 + lrow) * SROW * 2
                                                + lcol * 16 + ks * 32);
                asm volatile("ldmatrix.sync.aligned.m8n8.x4.trans.shared.b16 {%0,%1,%2,%3}, [%4];"
                             : "=r"(bf[0]), "=r"(bf[1]), "=r"(bf[2]), "=r"(bf[3])
                             : "r"(addr));
#pragma unroll
                for (int mi = 0; mi < 2; mi++) {
                    asm volatile(
                        "mma.sync.aligned.m16n8k16.row.col.f32.f16.f16.f32 "
                        "{%0,%1,%2,%3}, {%4,%5,%6,%7}, {%8,%9}, {%0,%1,%2,%3};"
                        : "+f"(d[mi][bj * 2][0]), "+f"(d[mi][bj * 2][1]),
                          "+f"(d[mi][bj * 2][2]), "+f"(d[mi][bj * 2][3])
                        : "r"(af[mi][0]), "r"(af[mi][1]), "r"(af[mi][2]), "r"(af[mi][3]),
                          "r"(bf[0]), "r"(bf[2]));
                    asm volatile(
                        "mma.sync.aligned.m16n8k16.row.col.f32.f16.f16.f32 "
                        "{%0,%1,%2,%3}, {%4,%5,%6,%7}, {%8,%9}, {%0,%1,%2,%3};"
                        : "+f"(d[mi][bj * 2 + 1][0]), "+f"(d[mi][bj * 2 + 1][1]),
                          "+f"(d[mi][bj * 2 + 1][2]), "+f"(d[mi][bj * 2 + 1][3])
                        : "r"(af[mi][0]), "r"(af[mi][1]), "r"(af[mi][2]), "r"(af[mi][3]),
                          "r"(bf[1]), "r"(bf[3]));
                }
            }
        }
        __syncthreads();
    }
}

// ---------------- generic 128x128 GEMM: fp32 out (+bias) ----------------
__global__ __launch_bounds__(256) void k_gemm(
    const __half* __restrict__ Aop, const __half* __restrict__ Bop,
    int Kld, int Klen, const float* __restrict__ bias,
    float* __restrict__ out, int ldo, int Nvalid, size_t slice_stride) {
    extern __shared__ __align__(16) __half dynsm[];
    const int tid = threadIdx.x;
    const int wid = tid >> 5, lane = tid & 31;
    const int wm = (wid & 3) * 32, wn = (wid >> 2) * 64;
    const int m0 = blockIdx.y * 128, n0 = blockIdx.x * 128;
    float d[2][8][4];
    gemm_mainloop<128>(Aop, Bop, Kld, Klen, blockIdx.z * Klen, m0, n0, dynsm, d);

    const int gid = lane >> 2, qid = lane & 3;
    float* obase = out + slice_stride * blockIdx.z;
#pragma unroll
    for (int mi = 0; mi < 2; mi++) {
        int r0 = m0 + wm + mi * 16 + gid;
#pragma unroll
        for (int nj = 0; nj < 8; nj++) {
            int col = n0 + wn + nj * 8 + qid * 2;
            if (col < Nvalid) {
                float b0 = bias ? bias[col] : 0.f;
                float b1 = bias ? bias[col + 1] : 0.f;
                float2 v0 = make_float2(d[mi][nj][0] + b0, d[mi][nj][1] + b1);
                float2 v1 = make_float2(d[mi][nj][2] + b0, d[mi][nj][3] + b1);
                *(float2*)&obase[(size_t)r0 * ldo + col] = v0;
                *(float2*)&obase[(size_t)(r0 + 8) * ldo + col] = v1;
            }
        }
    }
}

// ---------------- logits tile (BN=64) + fused log-softmax reduction ----------------
__device__ __forceinline__ void logits_tile64(int m0, int n0,
                                              const float* __restrict__ bias,
                                              __half* dynsm) {
    __shared__ float2 sred[128][2];
    __shared__ int tgt_sh[128];
    const int tid = threadIdx.x;
    const int wid = tid >> 5, lane = tid & 31;
    const int wm = (wid & 3) * 32, wn = (wid >> 2) * 32;
    if (tid < 128) tgt_sh[tid] = g_tgt[m0 + tid];
    float d[2][4][4];
    gemm_mainloop<64>(g_hsh, g_WvT, HD, HD, 0, m0, n0, dynsm, d);
    __syncthreads();   // tgt_sh visible to all

    const int gid = lane >> 2, qid = lane & 3;
    const int wcol = wid >> 2;   // 0..1
#pragma unroll
    for (int mi = 0; mi < 2; mi++) {
#pragma unroll
        for (int half = 0; half < 2; half++) {
            const int rl = wm + mi * 16 + gid + half * 8;
            const int mytgt = tgt_sh[rl];
            float vmax = -1e30f;
#pragma unroll
            for (int nj = 0; nj < 4; nj++) {
#pragma unroll
                for (int q = 0; q < 2; q++) {
                    int col = n0 + wn + nj * 8 + qid * 2 + q;
                    if (col < VOC)
                        vmax = fmaxf(vmax, d[mi][nj][half * 2 + q] + bias[col]);
                }
            }
#pragma unroll
            for (int off = 1; off < 4; off <<= 1)
                vmax = fmaxf(vmax, __shfl_xor_sync(0xFFFFFFFFu, vmax, off));
            float s = 0.f;
#pragma unroll
            for (int nj = 0; nj < 4; nj++) {
#pragma unroll
                for (int q = 0; q < 2; q++) {
                    int col = n0 + wn + nj * 8 + qid * 2 + q;
                    if (col < VOC) {
                        float v = d[mi][nj][half * 2 + q] + bias[col];
                        s += __expf(v - vmax);
                        if (col == mytgt) g_tgtlog[m0 + rl] = v;
                    }
                }
            }
#pragma unroll
            for (int off = 1; off < 4; off <<= 1)
                s += __shfl_xor_sync(0xFFFFFFFFu, s, off);
            if (qid == 0) sred[rl][wcol] = make_float2(vmax, s);
        }
    }
    __syncthreads();
    if (tid < 128) {
        float2 a = sred[tid][0], b = sred[tid][1];
        float M = fmaxf(a.x, b.x);
        float s = a.y * __expf(a.x - M) + b.y * __expf(b.x - M);
        unsigned long long* addr = &g_rowms[m0 + tid];
        unsigned long long old = *addr, assumed;
        do {
            assumed = old;
            float om = __uint_as_float((uint32_t)(assumed >> 32));
            float os = __uint_as_float((uint32_t)assumed);
            float NM = fmaxf(om, M);
            float ns = os * __expf(om - NM) + s * __expf(M - NM);
            unsigned long long nv =
                ((unsigned long long)__float_as_uint(NM) << 32) | __float_as_uint(ns);
            old = atomicCAS(addr, assumed, nv);
        } while (old != assumed);
    }
}

// ---------------- merged loop kernel: step GEMM + logits(t-1) ----------------
// blocks [0,128): step GEMM slice (n-tile, K-slice); blocks [128,288): logits tiles
__global__ __launch_bounds__(256) void k_merged(int t, const float* __restrict__ bias_v) {
    extern __shared__ __align__(16) __half dynsm[];
    const int b = blockIdx.x;
    if (b < 128) {
        const int n0 = (b & 31) * 128;
        const int z = b >> 5;
        const int Klen = 2 * HD / KSPLIT;   // 512
        const int tid = threadIdx.x;
        const int wid = tid >> 5, lane = tid & 31;
        const int wm = (wid & 3) * 32, wn = (wid >> 2) * 64;
        float d[2][8][4];
        gemm_mainloop<128>(g_hxh, g_WhaT, 2 * HD, Klen, z * Klen, 0, n0, dynsm, d);
        const int gid = lane >> 2, qid = lane & 3;
        float* obase = g_apart + (size_t)z * NB * 4 * HD;
#pragma unroll
        for (int mi = 0; mi < 2; mi++) {
            int r0 = wm + mi * 16 + gid;
#pragma unroll
            for (int nj = 0; nj < 8; nj++) {
                int col = n0 + wn + nj * 8 + qid * 2;
                float2 v0 = make_float2(d[mi][nj][0], d[mi][nj][1]);
                float2 v1 = make_float2(d[mi][nj][2], d[mi][nj][3]);
                *(float2*)&obase[(size_t)r0 * (4 * HD) + col] = v0;
                *(float2*)&obase[(size_t)(r0 + 8) * (4 * HD) + col] = v1;
            }
        }
    } else {
        if (t == 0) return;
        const int lb = b - 128;             // 0..159
        logits_tile64((t - 1) * 128, lb * 64, bias_v, dynsm);
    }
}

// tail: logits for the final step
__global__ __launch_bounds__(256) void k_logits_tail(int t, const float* __restrict__ bias_v) {
    extern __shared__ __align__(16) __half dynsm[];
    logits_tile64(t * 128, blockIdx.x * 64, bias_v, dynsm);
}

__global__ void k_loss() {
    int m = blockIdx.x * blockDim.x + threadIdx.x;
    if (m >= NROW) return;
    int tgt = g_tgt[m];
    if (tgt == 0) return;
    unsigned long long p = g_rowms[m];
    float M = __uint_as_float((uint32_t)(p >> 32));
    float s = __uint_as_float((uint32_t)p);
    atomicAdd(&g_loss, (M + logf(s)) - g_tgtlog[m]);
}

// ---------------- h0 = mean_p A ----------------
__global__ void k_h0() {
    int n = blockIdx.x;
    for (int h = threadIdx.x; h < HD; h += blockDim.x) {
        float s = 0.f;
#pragma unroll
        for (int p = 0; p < 16; p++) s += g_A[((size_t)n * 16 + p) * HD + h];
        s *= (1.0f / 16.0f);
        g_hx[(size_t)n * HD + h] = s;
        g_c[(size_t)n * HD + h] = s;
        g_hxh[(size_t)n * 2048 + h] = __float2half(s);
    }
}

// ---------------- fused LSTM(t) + attention ----------------
__global__ __launch_bounds__(512) void k_cell(int t) {
    const int n = blockIdx.x;
    __shared__ float h_sh[HD];
    __shared__ float sc[16];
    const int tid = threadIdx.x;

    if (t < 0) {
        h_sh[tid] = g_hx[(size_t)n * HD + tid];
        h_sh[tid + 512] = g_hx[(size_t)n * HD + tid + 512];
    } else {
        const float* xa = g_xa + ((size_t)t * NB + n) * 4096;
#pragma unroll
        for (int i = 0; i < 2; i++) {
            int h = tid + i * 512;
            float a0 = xa[h], a1 = xa[HD + h], a2 = xa[2 * HD + h], a3 = xa[3 * HD + h];
#pragma unroll
            for (int s = 0; s < KSPLIT; s++) {
                const float* p = g_apart + (size_t)s * NB * 4096 + (size_t)n * 4096;
                a0 += p[h]; a1 += p[HD + h]; a2 += p[2 * HD + h]; a3 += p[3 * HD + h];
            }
            float si = fast_sigmoid(a0);
            float sf = fast_sigmoid(a1);
            float so = fast_sigmoid(a2);
            float tg = fast_tanh(a3);
            size_t idx = (size_t)n * HD + h;
            float c = sf * g_c[idx] + si * tg;
            float hn = so * fast_tanh(c);
            g_c[idx] = c;
            h_sh[h] = hn;
            __half hh = __float2half(hn);
            g_hxh[(size_t)n * 2048 + h] = hh;
            g_hsh[((size_t)t * NB + n) * HD + h] = hh;
        }
    }
    __syncthreads();

    const int w = tid >> 5, lane = tid & 31;
    {
        const float* Arow = g_A + ((size_t)n * 16 + w) * HD;
        float s = 0.f;
        for (int h = lane; h < HD; h += 32) s += h_sh[h] * Arow[h];
#pragma unroll
        for (int o = 16; o; o >>= 1) s += __shfl_xor_sync(0xFFFFFFFFu, s, o);
        if (lane == 0) sc[w] = s * 0.03125f;
    }
    __syncthreads();
    float mx = sc[0];
#pragma unroll
    for (int p = 1; p < 16; p++) mx = fmaxf(mx, sc[p]);
    float wv[16];
    float sum = 0.f;
#pragma unroll
    for (int p = 0; p < 16; p++) { wv[p] = __expf(sc[p] - mx); sum += wv[p]; }
    const float inv = 1.0f / sum;
    for (int h = tid; h < HD; h += 512) {
        float a = 0.f;
#pragma unroll
        for (int p = 0; p < 16; p++) a += wv[p] * g_A[((size_t)n * 16 + p) * HD + h];
        g_hxh[(size_t)n * 2048 + HD + h] = __float2half(a * inv);
    }
}

// ---------------- launch ----------------
extern "C" void kernel_launch(void* const* d_in, const int* in_sizes, int n_in,
                              void* d_out, int out_size) {
    const float* images  = (const float*)d_in[0];
    const int*   caps    = (const int*)  d_in[1];
    const float* W_embed = (const float*)d_in[2];
    const float* W_proj  = (const float*)d_in[3];
    const float* b_proj  = (const float*)d_in[4];
    const float* Wx      = (const float*)d_in[5];
    const float* Wh      = (const float*)d_in[6];
    const float* Wattn   = (const float*)d_in[7];
    const float* bvec    = (const float*)d_in[8];
    const float* W_vocab = (const float*)d_in[9];
    const float* b_vocab = (const float*)d_in[10];
    float* out = (float*)d_out;

    // idempotent, called every launch (no static guards allowed)
    cudaFuncSetAttribute(k_gemm, cudaFuncAttributeMaxDynamicSharedMemorySize, DYN_SMEM_128);
    cudaFuncSetAttribute(k_merged, cudaFuncAttributeMaxDynamicSharedMemorySize, DYN_SMEM_128);
    cudaFuncSetAttribute(k_logits_tail, cudaFuncAttributeMaxDynamicSharedMemorySize, DYN_SMEM_64);

    float *pA, *pXa;
    cudaGetSymbolAddress((void**)&pA, g_A);
    cudaGetSymbolAddress((void**)&pXa, g_xa);
    __half *pWp, *pWx, *pWha, *pWv, *pAi, *pX;
    cudaGetSymbolAddress((void**)&pWp, g_WpT);
    cudaGetSymbolAddress((void**)&pWx, g_WxT);
    cudaGetSymbolAddress((void**)&pWha, g_WhaT);
    cudaGetSymbolAddress((void**)&pWv, g_WvT);
    cudaGetSymbolAddress((void**)&pAi, g_Ai);
    cudaGetSymbolAddress((void**)&pX, g_X);

    dim3 b32(32, 8);
    k_zero<<<1, 1>>>();
    k_prep<<<(NROW + 255) / 256, 256>>>(caps);
    k_convT<<<dim3(HD / 32, CIN / 32), b32>>>(W_proj, CIN, HD, pWp, CIN, 0);
    k_convT<<<dim3(4 * HD / 32, WD / 32), b32>>>(Wx, WD, 4 * HD, pWx, WD, 0);
    k_convT<<<dim3(4 * HD / 32, HD / 32), b32>>>(Wh, HD, 4 * HD, pWha, 2 * HD, 0);
    k_convT<<<dim3(4 * HD / 32, HD / 32), b32>>>(Wattn, HD, 4 * HD, pWha, 2 * HD, HD);
    k_convT<<<dim3(VOCP / 32, HD / 32), b32>>>(W_vocab, HD, VOC, pWv, HD, 0);
    k_conv_images<<<(NB * 16 * CIN + 255) / 256, 256>>>(images);
    k_conv_embed<<<(NROW * WD + 255) / 256, 256>>>(caps, W_embed);

    // image projection: [2048 x 1024]
    k_gemm<<<dim3(HD / 128, (NB * 16) / 128, 1), 256, DYN_SMEM_128>>>(
        pAi, pWp, CIN, CIN, b_proj, pA, HD, HD, 0);
    k_h0<<<NB, 256>>>();

    // xa: [3840 x 4096]
    k_gemm<<<dim3(4 * HD / 128, NROW / 128, 1), 256, DYN_SMEM_128>>>(
        pX, pWx, WD, WD, bvec, pXa, 4 * HD, 4 * HD, 0);

    k_cell<<<NB, 512>>>(-1);
    for (int t = 0; t < TSTEP; t++) {
        // step GEMM (128 CTAs) + logits(t-1) (160 CTAs) in one grid
        k_merged<<<288, 256, DYN_SMEM_128>>>(t, b_vocab);
        k_cell<<<NB, 512>>>(t);
    }
    k_logits_tail<<<VOCP / 64, 256, DYN_SMEM_64>>>(TSTEP - 1, b_vocab);

    k_loss<<<(NROW + 255) / 256, 256>>>();
    k_final<<<1, 1>>>(out);
}

// round 12
// speedup vs baseline: 4.2589x; 4.2589x over previous
#include <cuda_runtime.h>
#include <cuda_fp16.h>
#include <cstdint>
#include <math.h>

// ---------------- problem constants ----------------
#define NB    128
#define TCAP  31
#define TSTEP 30
#define CIN   1280
#define WD    512
#define HD    1024
#define VOC   10000
#define VOCP  10240
#define NROW  (TSTEP*NB)
#define KSPLIT 4
#define NTILE (VOCP/128)             // 80 logits n-tiles

#define SROW 40                      // smem row stride in halves (80B)
#define NSTAGE 3
#define DYN_SMEM (NSTAGE * (128 + 128) * SROW * 2)   // 61440

// ---------------- device scratch ----------------
__device__ float g_A[NB * 16 * HD];
__device__ float g_hx[NB * HD];
__device__ float g_c[NB * HD];
__device__ float g_xa[NROW * 4 * HD];
__device__ float g_apart[KSPLIT * NB * 4 * HD];
__device__ float2 g_pms[NROW * NTILE];   // per-(row,tile) softmax partials (max,sum)
__device__ float g_tgtlog[NROW];
__device__ int   g_tgt[NROW];
__device__ float g_loss;

__device__ __align__(256) __half g_WpT[HD * CIN];
__device__ __align__(256) __half g_WxT[4 * HD * WD];
__device__ __align__(256) __half g_WhaT[4 * HD * 2 * HD];
__device__ __align__(256) __half g_WvT[VOCP * HD];
__device__ __align__(256) __half g_Ai[NB * 16 * CIN];
__device__ __align__(256) __half g_X[NROW * WD];
__device__ __align__(256) __half g_hxh[NB * 2 * HD];
__device__ __align__(256) __half g_hsh[NROW * HD];

// ---------------- tiny utils ----------------
__global__ void k_final(float* __restrict__ out) { out[0] = g_loss * (1.0f / (float)NB); }

__device__ __forceinline__ uint32_t smem_u32(const void* p) {
    uint32_t a;
    asm("{ .reg .u64 t; cvta.to.shared.u64 t, %1; cvt.u32.u64 %0, t; }" : "=r"(a) : "l"(p));
    return a;
}
__device__ __forceinline__ float fast_sigmoid(float x) {
    return 1.0f / (1.0f + __expf(-x));
}
__device__ __forceinline__ float fast_tanh(float x) {
    float xc = fminf(fmaxf(x, -15.f), 15.f);
    float e = __expf(2.0f * xc);
    return (e - 1.0f) / (e + 1.0f);
}

// target gather + loss zero (k_zero folded in)
__global__ void k_prep(const int* __restrict__ captions) {
    int m = blockIdx.x * blockDim.x + threadIdx.x;
    if (m == 0) g_loss = 0.f;
    if (m >= NROW) return;
    int t = m >> 7, n = m & 127;
    g_tgt[m] = captions[n * TCAP + t + 1];
}

// ---------------- weight transpose fp32[K][N] -> fp16[N][dld] ----------------
__global__ void k_convT(const float* __restrict__ src, int K, int N,
                        __half* __restrict__ dst, int dld, int koff) {
    __shared__ float t[32][33];
    const int nb = blockIdx.x * 32, kb = blockIdx.y * 32;
    const int tx = threadIdx.x, ty = threadIdx.y;
#pragma unroll
    for (int i = 0; i < 4; i++) {
        int k = kb + ty + i * 8, n = nb + tx;
        t[ty + i * 8][tx] = (n < N && k < K) ? src[(size_t)k * N + n] : 0.f;
    }
    __syncthreads();
#pragma unroll
    for (int i = 0; i < 4; i++) {
        int n = nb + ty + i * 8, k = kb + tx;
        dst[(size_t)n * dld + koff + k] = __float2half(t[tx][ty + i * 8]);
    }
}

__global__ void k_conv_images(const float* __restrict__ images) {
    int idx = blockIdx.x * blockDim.x + threadIdx.x;
    if (idx >= NB * 16 * CIN) return;
    int m = idx / CIN, c = idx - m * CIN;
    g_Ai[idx] = __float2half(images[((size_t)(m >> 4) * CIN + c) * 16 + (m & 15)]);
}

__global__ void k_conv_embed(const int* __restrict__ captions,
                             const float* __restrict__ We) {
    int idx = blockIdx.x * blockDim.x + threadIdx.x;
    if (idx >= NROW * WD) return;
    int m = idx / WD, k = idx - m * WD;
    int t = m >> 7, n = m & 127;
    g_X[idx] = __float2half(We[(size_t)captions[n * TCAP + t] * WD + k]);
}

// ---------------- fp16 mma.sync mainloop (3-stage cp.async, BM=BN=128) ----------------
__device__ __forceinline__ void gemm_mainloop(
    const __half* __restrict__ Aop, const __half* __restrict__ Bop,
    int Kld, int Klen, int koff, int m0, int n0,
    __half* dynsm, float d[2][8][4]) {
    const int tid = threadIdx.x;
    const int wid = tid >> 5, lane = tid & 31;
    const int wm = (wid & 3) * 32;
    const int wn = (wid >> 2) * 64;
    const int KT = Klen >> 5;
    const uint32_t sbase = smem_u32(dynsm);
    const int lrow = lane & 15, lcol = lane >> 4;
    const uint32_t STB = (128 + 128) * SROW * 2;

#pragma unroll
    for (int i = 0; i < 2; i++)
#pragma unroll
        for (int j = 0; j < 8; j++)
#pragma unroll
            for (int q = 0; q < 4; q++) d[i][j][q] = 0.f;

    auto issue = [&](int kt) {
        const int stage = kt % NSTAGE;
        const uint32_t ab = sbase + (uint32_t)stage * STB;
        const uint32_t bb = ab + 128 * SROW * 2;
        const int k0 = koff + (kt << 5);
#pragma unroll
        for (int i = 0; i < 2; i++) {
            int c = tid + i * 256;
            int r = c >> 2, seg = c & 3;
            const void* gp = Aop + (size_t)(m0 + r) * Kld + k0 + seg * 8;
            uint32_t sp = ab + (uint32_t)(r * SROW * 2 + seg * 16);
            asm volatile("cp.async.cg.shared.global [%0], [%1], 16;" :: "r"(sp), "l"(gp));
        }
#pragma unroll
        for (int i = 0; i < 2; i++) {
            int c = tid + i * 256;
            int r = c >> 2, seg = c & 3;
            const void* gp = Bop + (size_t)(n0 + r) * Kld + k0 + seg * 8;
            uint32_t sp = bb + (uint32_t)(r * SROW * 2 + seg * 16);
            asm volatile("cp.async.cg.shared.global [%0], [%1], 16;" :: "r"(sp), "l"(gp));
        }
        asm volatile("cp.async.commit_group;");
    };

    issue(0);
    if (KT > 1) issue(1);
    for (int kt = 0; kt < KT; kt++) {
        if (kt + 2 < KT) {
            issue(kt + 2);
            asm volatile("cp.async.wait_group 2;");
        } else if (kt + 1 < KT) {
            asm volatile("cp.async.wait_group 1;");
        } else {
            asm volatile("cp.async.wait_group 0;");
        }
        __syncthreads();
        const int stage = kt % NSTAGE;
        const uint32_t ab = sbase + (uint32_t)stage * STB;
        const uint32_t bb = ab + 128 * SROW * 2;
#pragma unroll
        for (int ks = 0; ks < 2; ks++) {
            uint32_t af[2][4];
#pragma unroll
            for (int mi = 0; mi < 2; mi++) {
                uint32_t addr = ab + (uint32_t)((wm + mi * 16 + lrow) * SROW * 2
                                                + lcol * 16 + ks * 32);
                asm volatile("ldmatrix.sync.aligned.m8n8.x4.shared.b16 {%0,%1,%2,%3}, [%4];"
                             : "=r"(af[mi][0]), "=r"(af[mi][1]), "=r"(af[mi][2]), "=r"(af[mi][3])
                             : "r"(addr));
            }
#pragma unroll
            for (int bj = 0; bj < 4; bj++) {
                uint32_t bf[4];
                uint32_t addr = bb + (uint32_t)((wn + bj * 16 + lrow) * SROW * 2
                                                + lcol * 16 + ks * 32);
                asm volatile("ldmatrix.sync.aligned.m8n8.x4.trans.shared.b16 {%0,%1,%2,%3}, [%4];"
                             : "=r"(bf[0]), "=r"(bf[1]), "=r"(bf[2]), "=r"(bf[3])
                             : "r"(addr));
#pragma unroll
                for (int mi = 0; mi < 2; mi++) {
                    asm volatile(
                        "mma.sync.aligned.m16n8k16.row.col.f32.f16.f16.f32 "
                        "{%0,%1,%2,%3}, {%4,%5,%6,%7}, {%8,%9}, {%0,%1,%2,%3};"
                        : "+f"(d[mi][bj * 2][0]), "+f"(d[mi][bj * 2][1]),
                          "+f"(d[mi][bj * 2][2]), "+f"(d[mi][bj * 2][3])
                        : "r"(af[mi][0]), "r"(af[mi][1]), "r"(af[mi][2]), "r"(af[mi][3]),
                          "r"(bf[0]), "r"(bf[2]));
                    asm volatile(
                        "mma.sync.aligned.m16n8k16.row.col.f32.f16.f16.f32 "
                        "{%0,%1,%2,%3}, {%4,%5,%6,%7}, {%8,%9}, {%0,%1,%2,%3};"
                        : "+f"(d[mi][bj * 2 + 1][0]), "+f"(d[mi][bj * 2 + 1][1]),
                          "+f"(d[mi][bj * 2 + 1][2]), "+f"(d[mi][bj * 2 + 1][3])
                        : "r"(af[mi][0]), "r"(af[mi][1]), "r"(af[mi][2]), "r"(af[mi][3]),
                          "r"(bf[1]), "r"(bf[3]));
                }
            }
        }
        __syncthreads();
    }
}

// ---------------- generic 128x128 GEMM: fp32 out (+bias) ----------------
__global__ __launch_bounds__(256) void k_gemm(
    const __half* __restrict__ Aop, const __half* __restrict__ Bop,
    int Kld, int Klen, const float* __restrict__ bias,
    float* __restrict__ out, int ldo, int Nvalid, size_t slice_stride) {
    extern __shared__ __align__(16) __half dynsm[];
    const int tid = threadIdx.x;
    const int wid = tid >> 5, lane = tid & 31;
    const int wm = (wid & 3) * 32, wn = (wid >> 2) * 64;
    const int m0 = blockIdx.y * 128, n0 = blockIdx.x * 128;
    float d[2][8][4];
    gemm_mainloop(Aop, Bop, Kld, Klen, blockIdx.z * Klen, m0, n0, dynsm, d);

    const int gid = lane >> 2, qid = lane & 3;
    float* obase = out + slice_stride * blockIdx.z;
#pragma unroll
    for (int mi = 0; mi < 2; mi++) {
        int r0 = m0 + wm + mi * 16 + gid;
#pragma unroll
        for (int nj = 0; nj < 8; nj++) {
            int col = n0 + wn + nj * 8 + qid * 2;
            if (col < Nvalid) {
                float b0 = bias ? bias[col] : 0.f;
                float b1 = bias ? bias[col + 1] : 0.f;
                float2 v0 = make_float2(d[mi][nj][0] + b0, d[mi][nj][1] + b1);
                float2 v1 = make_float2(d[mi][nj][2] + b0, d[mi][nj][3] + b1);
                *(float2*)&obase[(size_t)r0 * ldo + col] = v0;
                *(float2*)&obase[(size_t)(r0 + 8) * ldo + col] = v1;
            }
        }
    }
}

// ---------------- logits GEMM + fused log-softmax partials (NO atomics) ----------------
// grid: (NTILE, NROW/128). Writes g_pms[row][tile] = (max, sumexp) and g_tgtlog.
__global__ __launch_bounds__(256) void k_gemm_lsm(
    const __half* __restrict__ Aop, const __half* __restrict__ Bop,
    const float* __restrict__ bias) {
    extern __shared__ __align__(16) __half dynsm[];
    __shared__ float2 sred[128][2];
    __shared__ int tgt_sh[128];
    const int tid = threadIdx.x;
    const int wid = tid >> 5, lane = tid & 31;
    const int wm = (wid & 3) * 32, wn = (wid >> 2) * 64;
    const int m0 = blockIdx.y * 128, n0 = blockIdx.x * 128;
    if (tid < 128) tgt_sh[tid] = g_tgt[m0 + tid];
    float d[2][8][4];
    gemm_mainloop(Aop, Bop, HD, HD, 0, m0, n0, dynsm, d);
    __syncthreads();   // tgt_sh visible

    const int gid = lane >> 2, qid = lane & 3;
    const int wcol = wid >> 2;
#pragma unroll
    for (int mi = 0; mi < 2; mi++) {
#pragma unroll
        for (int half = 0; half < 2; half++) {
            const int rl = wm + mi * 16 + gid + half * 8;
            const int mytgt = tgt_sh[rl];
            // pass 1: max
            float vmax = -1e30f;
#pragma unroll
            for (int nj = 0; nj < 8; nj++) {
#pragma unroll
                for (int q = 0; q < 2; q++) {
                    int col = n0 + wn + nj * 8 + qid * 2 + q;
                    if (col < VOC)
                        vmax = fmaxf(vmax, d[mi][nj][half * 2 + q] + bias[col]);
                }
            }
#pragma unroll
            for (int off = 1; off < 4; off <<= 1)
                vmax = fmaxf(vmax, __shfl_xor_sync(0xFFFFFFFFu, vmax, off));
            // pass 2: sum of exp + target capture
            float s = 0.f;
#pragma unroll
            for (int nj = 0; nj < 8; nj++) {
#pragma unroll
                for (int q = 0; q < 2; q++) {
                    int col = n0 + wn + nj * 8 + qid * 2 + q;
                    if (col < VOC) {
                        float v = d[mi][nj][half * 2 + q] + bias[col];
                        s += __expf(v - vmax);
                        if (col == mytgt) g_tgtlog[m0 + rl] = v;
                    }
                }
            }
#pragma unroll
            for (int off = 1; off < 4; off <<= 1)
                s += __shfl_xor_sync(0xFFFFFFFFu, s, off);
            if (qid == 0) sred[rl][wcol] = make_float2(vmax, s);
        }
    }
    __syncthreads();
    if (tid < 128) {
        float2 a = sred[tid][0], b = sred[tid][1];
        float M = fmaxf(a.x, b.x);
        float s = a.y * __expf(a.x - M) + b.y * __expf(b.x - M);
        g_pms[(size_t)(m0 + tid) * NTILE + blockIdx.x] = make_float2(M, s);
    }
}

// ---------------- loss: warp-per-row reduction over NTILE partials ----------------
__global__ __launch_bounds__(256) void k_loss() {
    const int wid = threadIdx.x >> 5, lane = threadIdx.x & 31;
    const int m = blockIdx.x * 8 + wid;
    __shared__ float bsum[8];
    float M = -1e30f, s = 0.f;
    for (int j = lane; j < NTILE; j += 32) {
        float2 p = g_pms[(size_t)m * NTILE + j];
        float NM = fmaxf(M, p.x);
        s = s * __expf(M - NM) + p.y * __expf(p.x - NM);
        M = NM;
    }
#pragma unroll
    for (int o = 16; o; o >>= 1) {
        float M2 = __shfl_xor_sync(0xFFFFFFFFu, M, o);
        float s2 = __shfl_xor_sync(0xFFFFFFFFu, s, o);
        float NM = fmaxf(M, M2);
        s = s * __expf(M - NM) + s2 * __expf(M2 - NM);
        M = NM;
    }
    if (lane == 0) {
        int tgt = g_tgt[m];
        bsum[wid] = (tgt != 0) ? (M + logf(s)) - g_tgtlog[m] : 0.f;
    }
    __syncthreads();
    if (threadIdx.x == 0) {
        float tsum = 0.f;
#pragma unroll
        for (int i = 0; i < 8; i++) tsum += bsum[i];
        atomicAdd(&g_loss, tsum);
    }
}

// ---------------- h0 = mean_p A ----------------
__global__ void k_h0() {
    int n = blockIdx.x;
    for (int h = threadIdx.x; h < HD; h += blockDim.x) {
        float s = 0.f;
#pragma unroll
        for (int p = 0; p < 16; p++) s += g_A[((size_t)n * 16 + p) * HD + h];
        s *= (1.0f / 16.0f);
        g_hx[(size_t)n * HD + h] = s;
        g_c[(size_t)n * HD + h] = s;
        g_hxh[(size_t)n * 2048 + h] = __float2half(s);
    }
}

// ---------------- fused LSTM(t) + attention ----------------
__global__ __launch_bounds__(512) void k_cell(int t) {
    const int n = blockIdx.x;
    __shared__ float h_sh[HD];
    __shared__ float sc[16];
    const int tid = threadIdx.x;

    if (t < 0) {
        h_sh[tid] = g_hx[(size_t)n * HD + tid];
        h_sh[tid + 512] = g_hx[(size_t)n * HD + tid + 512];
    } else {
        const float* xa = g_xa + ((size_t)t * NB + n) * 4096;
#pragma unroll
        for (int i = 0; i < 2; i++) {
            int h = tid + i * 512;
            float a0 = xa[h], a1 = xa[HD + h], a2 = xa[2 * HD + h], a3 = xa[3 * HD + h];
#pragma unroll
            for (int s = 0; s < KSPLIT; s++) {
                const float* p = g_apart + (size_t)s * NB * 4096 + (size_t)n * 4096;
                a0 += p[h]; a1 += p[HD + h]; a2 += p[2 * HD + h]; a3 += p[3 * HD + h];
            }
            float si = fast_sigmoid(a0);
            float sf = fast_sigmoid(a1);
            float so = fast_sigmoid(a2);
            float tg = fast_tanh(a3);
            size_t idx = (size_t)n * HD + h;
            float c = sf * g_c[idx] + si * tg;
            float hn = so * fast_tanh(c);
            g_c[idx] = c;
            h_sh[h] = hn;
            __half hh = __float2half(hn);
            g_hxh[(size_t)n * 2048 + h] = hh;
            g_hsh[((size_t)t * NB + n) * HD + h] = hh;
        }
    }
    __syncthreads();

    const int w = tid >> 5, lane = tid & 31;
    {
        const float* Arow = g_A + ((size_t)n * 16 + w) * HD;
        float s = 0.f;
        for (int h = lane; h < HD; h += 32) s += h_sh[h] * Arow[h];
#pragma unroll
        for (int o = 16; o; o >>= 1) s += __shfl_xor_sync(0xFFFFFFFFu, s, o);
        if (lane == 0) sc[w] = s * 0.03125f;
    }
    __syncthreads();
    float mx = sc[0];
#pragma unroll
    for (int p = 1; p < 16; p++) mx = fmaxf(mx, sc[p]);
    float wv[16];
    float sum = 0.f;
#pragma unroll
    for (int p = 0; p < 16; p++) { wv[p] = __expf(sc[p] - mx); sum += wv[p]; }
    const float inv = 1.0f / sum;
    for (int h = tid; h < HD; h += 512) {
        float a = 0.f;
#pragma unroll
        for (int p = 0; p < 16; p++) a += wv[p] * g_A[((size_t)n * 16 + p) * HD + h];
        g_hxh[(size_t)n * 2048 + HD + h] = __float2half(a * inv);
    }
}

// ---------------- launch ----------------
extern "C" void kernel_launch(void* const* d_in, const int* in_sizes, int n_in,
                              void* d_out, int out_size) {
    const float* images  = (const float*)d_in[0];
    const int*   caps    = (const int*)  d_in[1];
    const float* W_embed = (const float*)d_in[2];
    const float* W_proj  = (const float*)d_in[3];
    const float* b_proj  = (const float*)d_in[4];
    const float* Wx      = (const float*)d_in[5];
    const float* Wh      = (const float*)d_in[6];
    const float* Wattn   = (const float*)d_in[7];
    const float* bvec    = (const float*)d_in[8];
    const float* W_vocab = (const float*)d_in[9];
    const float* b_vocab = (const float*)d_in[10];
    float* out = (float*)d_out;

    cudaFuncSetAttribute(k_gemm, cudaFuncAttributeMaxDynamicSharedMemorySize, DYN_SMEM);
    cudaFuncSetAttribute(k_gemm_lsm, cudaFuncAttributeMaxDynamicSharedMemorySize, DYN_SMEM);

    float *pA, *pXa, *pApart;
    cudaGetSymbolAddress((void**)&pA, g_A);
    cudaGetSymbolAddress((void**)&pXa, g_xa);
    cudaGetSymbolAddress((void**)&pApart, g_apart);
    __half *pWp, *pWx, *pWha, *pWv, *pAi, *pX, *pHxh, *pHsh;
    cudaGetSymbolAddress((void**)&pWp, g_WpT);
    cudaGetSymbolAddress((void**)&pWx, g_WxT);
    cudaGetSymbolAddress((void**)&pWha, g_WhaT);
    cudaGetSymbolAddress((void**)&pWv, g_WvT);
    cudaGetSymbolAddress((void**)&pAi, g_Ai);
    cudaGetSymbolAddress((void**)&pX, g_X);
    cudaGetSymbolAddress((void**)&pHxh, g_hxh);
    cudaGetSymbolAddress((void**)&pHsh, g_hsh);

    dim3 b32(32, 8);
    k_prep<<<(NROW + 255) / 256, 256>>>(caps);
    k_convT<<<dim3(HD / 32, CIN / 32), b32>>>(W_proj, CIN, HD, pWp, CIN, 0);
    k_convT<<<dim3(4 * HD / 32, WD / 32), b32>>>(Wx, WD, 4 * HD, pWx, WD, 0);
    k_convT<<<dim3(4 * HD / 32, HD / 32), b32>>>(Wh, HD, 4 * HD, pWha, 2 * HD, 0);
    k_convT<<<dim3(4 * HD / 32, HD / 32), b32>>>(Wattn, HD, 4 * HD, pWha, 2 * HD, HD);
    k_convT<<<dim3(VOCP / 32, HD / 32), b32>>>(W_vocab, HD, VOC, pWv, HD, 0);
    k_conv_images<<<(NB * 16 * CIN + 255) / 256, 256>>>(images);
    k_conv_embed<<<(NROW * WD + 255) / 256, 256>>>(caps, W_embed);

    // image projection: [2048 x 1024]
    k_gemm<<<dim3(HD / 128, (NB * 16) / 128, 1), 256, DYN_SMEM>>>(
        pAi, pWp, CIN, CIN, b_proj, pA, HD, HD, 0);
    k_h0<<<NB, 256>>>();

    // xa: [3840 x 4096]
    k_gemm<<<dim3(4 * HD / 128, NROW / 128, 1), 256, DYN_SMEM>>>(
        pX, pWx, WD, WD, bvec, pXa, 4 * HD, 4 * HD, 0);

    k_cell<<<NB, 512>>>(-1);
    for (int t = 0; t < TSTEP; t++) {
        // step GEMM: [128 x 4096] = hx[128 x 2048] @ WhaT^T, split-K=4
        k_gemm<<<dim3(4 * HD / 128, 1, KSPLIT), 256, DYN_SMEM>>>(
            pHxh, pWha, 2 * HD, 2 * HD / KSPLIT, nullptr,
            pApart, 4 * HD, 4 * HD, (size_t)NB * 4 * HD);
        k_cell<<<NB, 512>>>(t);
    }

    // logits GEMM with fused log-softmax partials (atomic-free)
    k_gemm_lsm<<<dim3(NTILE, NROW / 128), 256, DYN_SMEM>>>(pHsh, pWv, b_vocab);
    k_loss<<<NROW / 8, 256>>>();
    k_final<<<1, 1>>>(out);
}